// round 9
// baseline (speedup 1.0000x reference)
#include <cuda_runtime.h>
#include <math.h>

// Problem constants
#define B 32
#define S 2048
#define D 1024
#define MASK_PENALTY 100000000.0f

// Tiling
#define NSPLIT 16
#define WARPS 4
#define THREADS (WARPS * 32)                    // 128
#define ROWS_PER_SPLIT (S / NSPLIT)             // 128 == THREADS

// Scratch (allocation-free: __device__ globals, zero-init)
__device__ float g_m[B * NSPLIT];
__device__ float g_l[B * NSPLIT];
__device__ __align__(16) float g_acc[(size_t)B * NSPLIT * D];  // 2 MB
__device__ int g_cnt[B];  // zero-init; self-resets each launch

// ---------------------------------------------------------------------------
// Fused single-pass online-softmax attention: mask skipping + compaction +
// TWO-ROW-PER-ITERATION pipeline.
// Masked rows contribute exp(-1e8)==0.0f exactly in fp32 -> skipped.
// The CTA compacts valid row indices into smem (deterministic ballot/popc),
// then each warp consumes PAIRS of valid rows: 16 LDG.128 (8KB) in flight
// per iteration, two interleaved butterfly reductions, ONE combined softmax
// update (acc = acc*scale + w1*c1 + w2*c2) -> half the serial windows.
// 4 warp partials merge in smem -> 1 per CTA -> last CTA per batch merges.
// ---------------------------------------------------------------------------
__global__ void __launch_bounds__(THREADS, 3)
attn_fused(const float* __restrict__ target,
           const float* __restrict__ context,
           const float* __restrict__ mask,
           float* __restrict__ out)
{
    const int b     = blockIdx.x;
    const int split = blockIdx.y;
    const int w     = threadIdx.x >> 5;
    const int lane  = threadIdx.x & 31;
    const int s0    = split * ROWS_PER_SPLIT;

    __shared__ short slist[ROWS_PER_SPLIT];   // compacted valid row indices
    __shared__ int   swcnt[WARPS];
    __shared__ int   scnt;
    __shared__ float sm_[WARPS];
    __shared__ float sl_[WARPS];
    __shared__ __align__(16) float4 sacc[WARPS][D / 4];   // 16 KB

    // ---- Deterministic compaction (all 128 threads, 1 row each) ----
    {
        const bool v = mask[(size_t)b * S + s0 + threadIdx.x] != 0.f;
        const unsigned bal = __ballot_sync(0xffffffffu, v);
        if (lane == 0) swcnt[w] = __popc(bal);
        __syncthreads();
        int off = 0;
#pragma unroll
        for (int i = 0; i < WARPS; i++) off += (i < w) ? swcnt[i] : 0;
        if (threadIdx.x == 0)
            scnt = swcnt[0] + swcnt[1] + swcnt[2] + swcnt[3];
        if (v) {
            const int pos = off + __popc(bal & ((1u << lane) - 1u));
            slist[pos] = (short)threadIdx.x;
        }
    }

    // Lane's slice of the query vector (registers)
    const float4* tg = (const float4*)(target + (size_t)b * D);
    float4 t[8];
#pragma unroll
    for (int i = 0; i < 8; i++) t[i] = tg[lane + 32 * i];

    __syncthreads();
    const int cnt = scnt;
    const int npairs = cnt >> 1;

    float4 acc[8];
#pragma unroll
    for (int i = 0; i < 8; i++) acc[i] = make_float4(0.f, 0.f, 0.f, 0.f);

    float m = -INFINITY;
    float l = 0.f;

    const float* cb = context + (size_t)b * S * D;

    // ---- Mainloop: two valid rows per iteration ----
    for (int q = w; q < npairs; q += WARPS) {
        const int r1 = slist[2 * q];
        const int r2 = slist[2 * q + 1];
        const float4* row1 = (const float4*)(cb + (size_t)(s0 + r1) * D);
        const float4* row2 = (const float4*)(cb + (size_t)(s0 + r2) * D);

        float4 c1[8], c2[8];
#pragma unroll
        for (int i = 0; i < 8; i++) c1[i] = row1[lane + 32 * i];
#pragma unroll
        for (int i = 0; i < 8; i++) c2[i] = row2[lane + 32 * i];

        // two dot products, two chains each
        float a0 = 0.f, a1 = 0.f, b0 = 0.f, b1 = 0.f;
#pragma unroll
        for (int i = 0; i < 8; i++) {
            a0 = fmaf(c1[i].x, t[i].x, a0);
            a1 = fmaf(c1[i].y, t[i].y, a1);
            a0 = fmaf(c1[i].z, t[i].z, a0);
            a1 = fmaf(c1[i].w, t[i].w, a1);
            b0 = fmaf(c2[i].x, t[i].x, b0);
            b1 = fmaf(c2[i].y, t[i].y, b1);
            b0 = fmaf(c2[i].z, t[i].z, b0);
            b1 = fmaf(c2[i].w, t[i].w, b1);
        }
        float dot1 = a0 + a1;
        float dot2 = b0 + b1;
        // interleaved butterfly reductions (independent chains overlap)
#pragma unroll
        for (int off = 16; off > 0; off >>= 1) {
            dot1 += __shfl_xor_sync(0xffffffffu, dot1, off);
            dot2 += __shfl_xor_sync(0xffffffffu, dot2, off);
        }

        // combined online-softmax update for both rows
        const float mnew = fmaxf(m, fmaxf(dot1, dot2));
        const float scale = __expf(m - mnew);     // 0 on first iteration
        const float w1 = __expf(dot1 - mnew);
        const float w2 = __expf(dot2 - mnew);
        l = l * scale + (w1 + w2);
#pragma unroll
        for (int i = 0; i < 8; i++) {
            acc[i].x = fmaf(acc[i].x, scale, fmaf(w1, c1[i].x, w2 * c2[i].x));
            acc[i].y = fmaf(acc[i].y, scale, fmaf(w1, c1[i].y, w2 * c2[i].y));
            acc[i].z = fmaf(acc[i].z, scale, fmaf(w1, c1[i].z, w2 * c2[i].z));
            acc[i].w = fmaf(acc[i].w, scale, fmaf(w1, c1[i].w, w2 * c2[i].w));
        }
        m = mnew;
    }

    // Odd leftover row handled by the warp whose turn it would be
    if ((cnt & 1) && (w == (npairs & (WARPS - 1)))) {
        const int r = slist[cnt - 1];
        const float4* row = (const float4*)(cb + (size_t)(s0 + r) * D);
        float4 c[8];
#pragma unroll
        for (int i = 0; i < 8; i++) c[i] = row[lane + 32 * i];
        float a0 = 0.f, a1 = 0.f;
#pragma unroll
        for (int i = 0; i < 8; i++) {
            a0 = fmaf(c[i].x, t[i].x, a0);
            a1 = fmaf(c[i].y, t[i].y, a1);
            a0 = fmaf(c[i].z, t[i].z, a0);
            a1 = fmaf(c[i].w, t[i].w, a1);
        }
        float dot = a0 + a1;
#pragma unroll
        for (int off = 16; off > 0; off >>= 1)
            dot += __shfl_xor_sync(0xffffffffu, dot, off);
        const float mnew  = fmaxf(m, dot);
        const float scale = __expf(m - mnew);
        const float wgt   = __expf(dot - mnew);
        l = l * scale + wgt;
#pragma unroll
        for (int i = 0; i < 8; i++) {
            acc[i].x = fmaf(acc[i].x, scale, wgt * c[i].x);
            acc[i].y = fmaf(acc[i].y, scale, wgt * c[i].y);
            acc[i].z = fmaf(acc[i].z, scale, wgt * c[i].z);
            acc[i].w = fmaf(acc[i].w, scale, wgt * c[i].w);
        }
        m = mnew;
    }

    // ---- In-CTA merge of the 4 warp partials ----
    if (lane == 0) { sm_[w] = m; sl_[w] = l; }
    __syncthreads();

    float Mcta = -INFINITY;
#pragma unroll
    for (int i = 0; i < WARPS; i++) Mcta = fmaxf(Mcta, sm_[i]);

    // Guard: warp with zero valid rows has m=-inf (Mcta may also be -inf).
    const float f = (m > -INFINITY) ? __expf(m - Mcta) : 0.f;
#pragma unroll
    for (int i = 0; i < 8; i++) {
        float4 a = acc[i];
        a.x *= f; a.y *= f; a.z *= f; a.w *= f;
        sacc[w][lane + 32 * i] = a;
    }
    __syncthreads();

    // 128 threads sum across 4 warps; each thread owns 2 float4 positions
    const int pidx = b * NSPLIT + split;
#pragma unroll
    for (int h = 0; h < 2; h++) {
        const int d4 = threadIdx.x + h * THREADS;
        float4 sum = sacc[0][d4];
#pragma unroll
        for (int i = 1; i < WARPS; i++) {
            const float4 v = sacc[i][d4];
            sum.x += v.x; sum.y += v.y; sum.z += v.z; sum.w += v.w;
        }
        ((float4*)(g_acc + (size_t)pidx * D))[d4] = sum;
    }

    if (threadIdx.x == 0) {
        float L = 0.f;
#pragma unroll
        for (int i = 0; i < WARPS; i++)
            L += (sm_[i] > -INFINITY ? __expf(sm_[i] - Mcta) : 0.f) * sl_[i];
        g_m[pidx] = Mcta;   // -inf if the whole split is masked
        g_l[pidx] = L;
    }

    // ---- Last CTA per batch merges the NSPLIT partials ----
    __threadfence();
    __syncthreads();
    __shared__ int isLast;
    if (threadIdx.x == 0)
        isLast = (atomicAdd(&g_cnt[b], 1) == NSPLIT - 1);
    __syncthreads();
    if (!isLast) return;
    __threadfence();  // acquire

    float pm[NSPLIT], pl[NSPLIT];
#pragma unroll
    for (int p = 0; p < NSPLIT; p++) {
        pm[p] = __ldcg(&g_m[b * NSPLIT + p]);
        pl[p] = __ldcg(&g_l[b * NSPLIT + p]);
    }
    // M is finite: position 0 of every batch is guaranteed valid.
    float M = -INFINITY;
#pragma unroll
    for (int p = 0; p < NSPLIT; p++) M = fmaxf(M, pm[p]);
    float L = 0.f;
#pragma unroll
    for (int p = 0; p < NSPLIT; p++)
        L += (pm[p] > -INFINITY ? __expf(pm[p] - M) : 0.f) * pl[p];
    const float Linv = 1.f / L;

#pragma unroll
    for (int h = 0; h < 2; h++) {
        const int d4 = threadIdx.x + h * THREADS;
        float4 a = make_float4(0.f, 0.f, 0.f, 0.f);
#pragma unroll
        for (int p = 0; p < NSPLIT; p++) {
            const float fp = (pm[p] > -INFINITY) ? __expf(pm[p] - M) : 0.f;
            const float4 v =
                __ldcg((const float4*)(g_acc + (size_t)(b * NSPLIT + p) * D) + d4);
            a.x = fmaf(fp, v.x, a.x);
            a.y = fmaf(fp, v.y, a.y);
            a.z = fmaf(fp, v.z, a.z);
            a.w = fmaf(fp, v.w, a.w);
        }
        a.x *= Linv; a.y *= Linv; a.z *= Linv; a.w *= Linv;
        ((float4*)(out + (size_t)b * D))[d4] = a;
    }

    if (threadIdx.x == 0) atomicExch(&g_cnt[b], 0);
}

extern "C" void kernel_launch(void* const* d_in, const int* in_sizes, int n_in,
                              void* d_out, int out_size)
{
    const float* target  = (const float*)d_in[0];  // [B, D]
    const float* context = (const float*)d_in[1];  // [B, S, D]
    const float* mask    = (const float*)d_in[2];  // [B, S]
    float* out = (float*)d_out;                    // [B, D]

    dim3 grid(B, NSPLIT);
    attn_fused<<<grid, THREADS>>>(target, context, mask, out);
}